// round 4
// baseline (speedup 1.0000x reference)
#include <cuda_runtime.h>

#define BB 64
#define CC 2048
#define DD 512
#define MM 128
#define NNEG 1920
#define TT 100
#define EPS 1e-6f

// scratch (allocation-free rule: __device__ globals)
__device__ float g_inv[BB * CC];                     // 1/||row||
__device__ unsigned long long g_best[BB * MM];       // packed (ordered_sim<<32)|(0x7FFFFFFF-n)

// ---------------------------------------------------------------------------
// K0: init scratch + output (runs every replay -> deterministic)
// ---------------------------------------------------------------------------
__global__ void k0_init(float* out) {
    int i = blockIdx.x * blockDim.x + threadIdx.x;
    if (i < BB * MM) g_best[i] = 0ULL;               // ordered-encoding: 0 < enc(x) for all real x
    if (i == 0) out[0] = 0.0f;
}

// ---------------------------------------------------------------------------
// K1: per-row inverse norms (reads the full 256MB tensor, streaming)
// one warp per row, float4 loads
// ---------------------------------------------------------------------------
__global__ __launch_bounds__(256) void k1_norm(const float* __restrict__ emb) {
    int row  = blockIdx.x * 8 + (threadIdx.x >> 5);
    int lane = threadIdx.x & 31;
    const float4* p = reinterpret_cast<const float4*>(emb + (size_t)row * DD);
    float ss = 0.0f;
#pragma unroll
    for (int q = 0; q < 4; q++) {
        float4 v = p[lane + 32 * q];
        ss += v.x * v.x + v.y * v.y + v.z * v.z + v.w * v.w;
    }
#pragma unroll
    for (int off = 16; off; off >>= 1)
        ss += __shfl_xor_sync(0xffffffffu, ss, off);
    if (lane == 0)
        g_inv[row] = 1.0f / fmaxf(sqrtf(ss), 1e-12f);
}

// ---------------------------------------------------------------------------
// K2: hard-negative mining.
// Per batch: sim[m][n] = dot(muc_m, non_n) for ALL 128 muc rows x 64-wide non
// tile, full K=512. Tiled fp32 GEMM, 256 threads (16x16), 8x4 outputs/thread.
// Thread (tx,ty): m = ty*8 + i (contiguous 8 rows -> float4 LDS on A side),
//                 n = n0 + tx + 16*j.
// Then 16-lane argmax reduce + packed atomicMax merge into g_best.
// ---------------------------------------------------------------------------
__device__ __forceinline__ unsigned ordered_f32(float v) {
    unsigned u = __float_as_uint(v);
    return (u & 0x80000000u) ? ~u : (u | 0x80000000u);
}

__global__ __launch_bounds__(256, 2) void k2_mine(const float* __restrict__ emb,
                                                  const int* __restrict__ muc,
                                                  const int* __restrict__ non) {
    __shared__ float As[16][128];   // [k][m]
    __shared__ float Bs[16][64];    // [k][n]
    __shared__ int   rA[128];
    __shared__ float sA[128];
    __shared__ int   rB[64];
    __shared__ float sB[64];

    const int b   = blockIdx.y;
    const int n0  = blockIdx.x * 64;
    const int tid = threadIdx.x;

    if (tid < 128) {
        int r = muc[b * MM + tid];
        rA[tid] = r;
        sA[tid] = g_inv[b * CC + r];
    } else if (tid < 192) {
        int t2 = tid - 128;
        int r = non[b * NNEG + n0 + t2];
        rB[t2] = r;
        sB[t2] = g_inv[b * CC + r];
    }
    __syncthreads();

    const int tx = tid & 15;    // n direction
    const int ty = tid >> 4;    // m direction: owns rows ty*8 .. ty*8+7

    float acc[8][4];
#pragma unroll
    for (int i = 0; i < 8; i++)
#pragma unroll
        for (int j = 0; j < 4; j++) acc[i][j] = 0.0f;

    const float* embB = emb + (size_t)b * CC * DD;

    for (int k0 = 0; k0 < DD; k0 += 16) {
        // stage A tile: 128 rows x 16 k  (512 float4, 2 per thread)
#pragma unroll
        for (int u = 0; u < 2; u++) {
            int f   = tid + u * 256;
            int row = f >> 2;
            int kq  = f & 3;
            float4 v = *reinterpret_cast<const float4*>(
                embB + (size_t)rA[row] * DD + k0 + kq * 4);
            float s = sA[row];
            As[kq * 4 + 0][row] = v.x * s;
            As[kq * 4 + 1][row] = v.y * s;
            As[kq * 4 + 2][row] = v.z * s;
            As[kq * 4 + 3][row] = v.w * s;
        }
        // stage B tile: 64 rows x 16 k (256 float4, 1 per thread)
        {
            int row = tid >> 2;
            int kq  = tid & 3;
            float4 v = *reinterpret_cast<const float4*>(
                embB + (size_t)rB[row] * DD + k0 + kq * 4);
            float s = sB[row];
            Bs[kq * 4 + 0][row] = v.x * s;
            Bs[kq * 4 + 1][row] = v.y * s;
            Bs[kq * 4 + 2][row] = v.z * s;
            Bs[kq * 4 + 3][row] = v.w * s;
        }
        __syncthreads();

#pragma unroll
        for (int k = 0; k < 16; k++) {
            // A fragment: 8 contiguous m rows -> two float4 LDS
            float4 a0 = *reinterpret_cast<const float4*>(&As[k][ty * 8]);
            float4 a1 = *reinterpret_cast<const float4*>(&As[k][ty * 8 + 4]);
            float a[8] = {a0.x, a0.y, a0.z, a0.w, a1.x, a1.y, a1.z, a1.w};
            float bb[4];
#pragma unroll
            for (int j = 0; j < 4; j++) bb[j] = Bs[k][tx + 16 * j];
#pragma unroll
            for (int i = 0; i < 8; i++)
#pragma unroll
                for (int j = 0; j < 4; j++)
                    acc[i][j] = fmaf(a[i], bb[j], acc[i][j]);
        }
        __syncthreads();
    }

    // per-thread argmax over its 4 n's, then 16-lane (same m-group) reduce
#pragma unroll
    for (int i = 0; i < 8; i++) {
        float val = acc[i][0];
        int   idx = n0 + tx;
#pragma unroll
        for (int j = 1; j < 4; j++) {
            int nn_ = n0 + tx + 16 * j;
            if (acc[i][j] > val || (acc[i][j] == val && nn_ < idx)) {
                val = acc[i][j];
                idx = nn_;
            }
        }
#pragma unroll
        for (int off = 8; off; off >>= 1) {
            float ov = __shfl_xor_sync(0xffffffffu, val, off);
            int   oi = __shfl_xor_sync(0xffffffffu, idx, off);
            if (ov > val || (ov == val && oi < idx)) {
                val = ov;
                idx = oi;
            }
        }
        if (tx == 0) {
            unsigned long long key =
                ((unsigned long long)ordered_f32(val) << 32) |
                (unsigned)(0x7FFFFFFFu - idx);
            atomicMax(&g_best[b * MM + ty * 8 + i], key);
        }
    }
}

// ---------------------------------------------------------------------------
// K3: loss. One warp per (b,t): d_pos, d_neg, relu(d_pos-d_neg+1), atomicAdd.
// ---------------------------------------------------------------------------
__global__ __launch_bounds__(256) void k3_loss(const float* __restrict__ emb,
                                               const int* __restrict__ muc,
                                               const int* __restrict__ non,
                                               const int* __restrict__ anc,
                                               const int* __restrict__ pos,
                                               float* __restrict__ out) {
    int g    = blockIdx.x * blockDim.x + threadIdx.x;
    int w    = g >> 5;
    int lane = g & 31;
    if (w >= BB * TT) return;
    int b = w / TT;
    int t = w % TT;

    int m  = anc[b * TT + t];
    int ra = muc[b * MM + m];
    int rp = muc[b * MM + pos[b * TT + t]];

    unsigned long long key = g_best[b * MM + m];
    int n  = (int)(0x7FFFFFFFu - (unsigned)(key & 0xFFFFFFFFu));
    int rn = non[b * NNEG + n];

    const float4* pa = reinterpret_cast<const float4*>(emb + ((size_t)b * CC + ra) * DD);
    const float4* pp = reinterpret_cast<const float4*>(emb + ((size_t)b * CC + rp) * DD);
    const float4* pn = reinterpret_cast<const float4*>(emb + ((size_t)b * CC + rn) * DD);
    float ia = g_inv[b * CC + ra];
    float ip = g_inv[b * CC + rp];
    float in_ = g_inv[b * CC + rn];

    float ssp = 0.0f, ssn = 0.0f;
#pragma unroll
    for (int q = 0; q < 4; q++) {
        int o = lane + 32 * q;
        float4 va = pa[o];
        float4 vp = pp[o];
        float4 vn = pn[o];
        float d;
        d = va.x * ia - vp.x * ip + EPS; ssp = fmaf(d, d, ssp);
        d = va.y * ia - vp.y * ip + EPS; ssp = fmaf(d, d, ssp);
        d = va.z * ia - vp.z * ip + EPS; ssp = fmaf(d, d, ssp);
        d = va.w * ia - vp.w * ip + EPS; ssp = fmaf(d, d, ssp);
        d = va.x * ia - vn.x * in_ + EPS; ssn = fmaf(d, d, ssn);
        d = va.y * ia - vn.y * in_ + EPS; ssn = fmaf(d, d, ssn);
        d = va.z * ia - vn.z * in_ + EPS; ssn = fmaf(d, d, ssn);
        d = va.w * ia - vn.w * in_ + EPS; ssn = fmaf(d, d, ssn);
    }
#pragma unroll
    for (int off = 16; off; off >>= 1) {
        ssp += __shfl_xor_sync(0xffffffffu, ssp, off);
        ssn += __shfl_xor_sync(0xffffffffu, ssn, off);
    }
    if (lane == 0) {
        float term = sqrtf(ssp) - sqrtf(ssn) + 1.0f;   // margin = 1.0
        term = fmaxf(term, 0.0f);
        atomicAdd(out, term * (1.0f / (float)(BB * TT)));
    }
}

// ---------------------------------------------------------------------------
extern "C" void kernel_launch(void* const* d_in, const int* in_sizes, int n_in,
                              void* d_out, int out_size) {
    const float* emb = (const float*)d_in[0];
    const int*   muc = (const int*)d_in[1];
    const int*   non = (const int*)d_in[2];
    const int*   anc = (const int*)d_in[3];
    const int*   pos = (const int*)d_in[4];
    float* out = (float*)d_out;

    k0_init<<<(BB * MM + 255) / 256, 256>>>(out);
    k1_norm<<<(BB * CC) / 8, 256>>>(emb);
    dim3 g2(NNEG / 64, BB);
    k2_mine<<<g2, 256>>>(emb, muc, non);
    k3_loss<<<(BB * TT * 32 + 255) / 256, 256>>>(emb, muc, non, anc, pos, out);
}

// round 6
// speedup vs baseline: 1.0162x; 1.0162x over previous
#include <cuda_runtime.h>
#include <cuda_bf16.h>
#include <mma.h>

using namespace nvcuda;

#define BB 64
#define CC 2048
#define DD 512
#define MM 128
#define NNEG 1920
#define TT 100
#define EPS 1e-6f

// scratch (allocation-free rule: __device__ globals; small!)
__device__ float g_inv[BB * CC];                       // 1/||row||
__device__ unsigned long long g_best[BB * MM];         // packed (ordered_sim<<32)|(0x7FFFFFFF-n)

// ---------------------------------------------------------------------------
// K0: init scratch + output
// ---------------------------------------------------------------------------
__global__ void k0_init(float* out) {
    int i = blockIdx.x * blockDim.x + threadIdx.x;
    if (i < BB * MM) g_best[i] = 0ULL;                 // ordered-encoding: 0 < enc(x) for all x
    if (i == 0) out[0] = 0.0f;
}

// ---------------------------------------------------------------------------
// K1: per-row inverse norms (streaming read of 256MB)
// ---------------------------------------------------------------------------
__global__ __launch_bounds__(256) void k1_norm(const float* __restrict__ emb) {
    int row  = blockIdx.x * 8 + (threadIdx.x >> 5);
    int lane = threadIdx.x & 31;
    const float4* p = reinterpret_cast<const float4*>(emb + (size_t)row * DD);
    float ss = 0.0f;
#pragma unroll
    for (int q = 0; q < 4; q++) {
        float4 v = p[lane + 32 * q];
        ss += v.x * v.x + v.y * v.y + v.z * v.z + v.w * v.w;
    }
#pragma unroll
    for (int off = 16; off; off >>= 1)
        ss += __shfl_xor_sync(0xffffffffu, ss, off);
    if (lane == 0)
        g_inv[row] = 1.0f / fmaxf(sqrtf(ss), 1e-12f);
}

// ---------------------------------------------------------------------------
// K2: hard-negative mining via bf16 WMMA tensor-core GEMM.
// Block = (batch b, n-tile of 128). Stages fp32 rows from emb, scales by
// g_inv, converts to bf16 into SMEM, then wmma 16x16x16 bf16/f32-acc.
// 8 warps as 2(M) x 4(N); warp tile 64x32 = 4x2 frags. K-chunk 64.
// Epilogue: C through SMEM overlay, per-m argmax, packed atomicMax merge.
// ---------------------------------------------------------------------------
__device__ __forceinline__ unsigned ordered_f32(float v) {
    unsigned u = __float_as_uint(v);
    return (u & 0x80000000u) ? ~u : (u | 0x80000000u);
}

#define KC   64            // k-chunk
#define LDT  72            // tile leading dim (bf16 elems): 144B rows, conflict-staggered
#define LDC  68            // C leading dim (f32 elems)

__global__ __launch_bounds__(256) void k2_mine(const float* __restrict__ emb,
                                               const int* __restrict__ muc,
                                               const int* __restrict__ non) {
    __shared__ __align__(16) char sbuf[2 * 128 * LDT * 2];   // As + Bs (36.9KB), overlaid by Csh
    __shared__ int   rA[128];
    __shared__ float sA[128];
    __shared__ int   rB[128];
    __shared__ float sB[128];

    __nv_bfloat16* As = reinterpret_cast<__nv_bfloat16*>(sbuf);            // [128][LDT]
    __nv_bfloat16* Bs = As + 128 * LDT;                                    // [128][LDT]
    float (*Csh)[LDC]  = reinterpret_cast<float (*)[LDC]>(sbuf);           // [128][LDC] overlay

    const int b   = blockIdx.y;
    const int n0  = blockIdx.x * 128;
    const int tid = threadIdx.x;
    const int warp   = tid >> 5;
    const int warp_m = warp >> 2;       // 0..1 -> rows warp_m*64
    const int warp_n = warp & 3;        // 0..3 -> cols warp_n*32

    if (tid < 128) {
        int r = muc[b * MM + tid];
        rA[tid] = r;
        sA[tid] = g_inv[b * CC + r];
    } else {
        int t2 = tid - 128;
        int r = non[b * NNEG + n0 + t2];
        rB[t2] = r;
        sB[t2] = g_inv[b * CC + r];
    }
    __syncthreads();

    wmma::fragment<wmma::accumulator, 16, 16, 16, float> acc[4][2];
#pragma unroll
    for (int i = 0; i < 4; i++)
#pragma unroll
        for (int j = 0; j < 2; j++)
            wmma::fill_fragment(acc[i][j], 0.0f);

    const float* embB = emb + (size_t)b * CC * DD;

    for (int k0 = 0; k0 < DD; k0 += KC) {
        // stage tiles: 128 rows x 64 fp32 each -> scale -> bf16.
        // per tile: 128*16 = 2048 float4 loads, 8 per thread.
#pragma unroll
        for (int u = 0; u < 8; u++) {
            int f    = tid + 256 * u;
            int row  = f >> 4;          // 0..127
            int colq = f & 15;          // float4 index within 64 floats
            // A tile
            {
                float4 v = *(reinterpret_cast<const float4*>(
                    embB + (size_t)rA[row] * DD + k0) + colq);
                float s = sA[row];
                __nv_bfloat162 lo = __floats2bfloat162_rn(v.x * s, v.y * s);
                __nv_bfloat162 hi = __floats2bfloat162_rn(v.z * s, v.w * s);
                uint2 w;
                w.x = *reinterpret_cast<unsigned*>(&lo);
                w.y = *reinterpret_cast<unsigned*>(&hi);
                *reinterpret_cast<uint2*>(As + row * LDT + colq * 4) = w;
            }
            // B tile
            {
                float4 v = *(reinterpret_cast<const float4*>(
                    embB + (size_t)rB[row] * DD + k0) + colq);
                float s = sB[row];
                __nv_bfloat162 lo = __floats2bfloat162_rn(v.x * s, v.y * s);
                __nv_bfloat162 hi = __floats2bfloat162_rn(v.z * s, v.w * s);
                uint2 w;
                w.x = *reinterpret_cast<unsigned*>(&lo);
                w.y = *reinterpret_cast<unsigned*>(&hi);
                *reinterpret_cast<uint2*>(Bs + row * LDT + colq * 4) = w;
            }
        }
        __syncthreads();

#pragma unroll
        for (int kf = 0; kf < KC / 16; kf++) {
            wmma::fragment<wmma::matrix_a, 16, 16, 16, __nv_bfloat16, wmma::row_major> af[4];
            wmma::fragment<wmma::matrix_b, 16, 16, 16, __nv_bfloat16, wmma::col_major> bf[2];
#pragma unroll
            for (int i = 0; i < 4; i++)
                wmma::load_matrix_sync(af[i], As + (warp_m * 64 + i * 16) * LDT + kf * 16, LDT);
#pragma unroll
            for (int j = 0; j < 2; j++)
                wmma::load_matrix_sync(bf[j], Bs + (warp_n * 32 + j * 16) * LDT + kf * 16, LDT);
#pragma unroll
            for (int i = 0; i < 4; i++)
#pragma unroll
                for (int j = 0; j < 2; j++)
                    wmma::mma_sync(acc[i][j], af[i], bf[j], acc[i][j]);
        }
        __syncthreads();
    }

    // epilogue: two 64-col halves through Csh (overlays As/Bs), per-m argmax
    const int m_of = tid >> 1;          // 0..127
    const int part = tid & 1;           // each handles 32 n per half
    float bestv = -1e30f;
    int   besti = 0;

#pragma unroll
    for (int half = 0; half < 2; half++) {
        __syncthreads();
        if ((warp_n >> 1) == half) {
#pragma unroll
            for (int i = 0; i < 4; i++)
#pragma unroll
                for (int j = 0; j < 2; j++)
                    wmma::store_matrix_sync(&Csh[warp_m * 64 + i * 16][(warp_n & 1) * 32 + j * 16],
                                            acc[i][j], LDC, wmma::mem_row_major);
        }
        __syncthreads();
#pragma unroll 8
        for (int jj = 0; jj < 32; jj++) {
            float v = Csh[m_of][part * 32 + jj];
            int  gn = n0 + half * 64 + part * 32 + jj;
            if (v > bestv) { bestv = v; besti = gn; }   // ascending scan -> first max wins ties
        }
    }
    // merge the two parts of each m (lanes 2t, 2t+1 in same warp)
    float ov = __shfl_xor_sync(0xffffffffu, bestv, 1);
    int   oi = __shfl_xor_sync(0xffffffffu, besti, 1);
    if (ov > bestv || (ov == bestv && oi < besti)) { bestv = ov; besti = oi; }
    if (part == 0) {
        unsigned long long key =
            ((unsigned long long)ordered_f32(bestv) << 32) |
            (unsigned)(0x7FFFFFFFu - besti);
        atomicMax(&g_best[b * MM + m_of], key);
    }
}

// ---------------------------------------------------------------------------
// K3: loss. One warp per (b,t): d_pos, d_neg (exact fp32), relu, atomicAdd.
// ---------------------------------------------------------------------------
__global__ __launch_bounds__(256) void k3_loss(const float* __restrict__ emb,
                                               const int* __restrict__ muc,
                                               const int* __restrict__ non,
                                               const int* __restrict__ anc,
                                               const int* __restrict__ pos,
                                               float* __restrict__ out) {
    int g    = blockIdx.x * blockDim.x + threadIdx.x;
    int w    = g >> 5;
    int lane = g & 31;
    if (w >= BB * TT) return;
    int b = w / TT;
    int t = w % TT;

    int m  = anc[b * TT + t];
    int ra = muc[b * MM + m];
    int rp = muc[b * MM + pos[b * TT + t]];

    unsigned long long key = g_best[b * MM + m];
    int n  = (int)(0x7FFFFFFFu - (unsigned)(key & 0xFFFFFFFFu));
    int rn = non[b * NNEG + n];

    const float4* pa = reinterpret_cast<const float4*>(emb + ((size_t)b * CC + ra) * DD);
    const float4* pp = reinterpret_cast<const float4*>(emb + ((size_t)b * CC + rp) * DD);
    const float4* pn = reinterpret_cast<const float4*>(emb + ((size_t)b * CC + rn) * DD);
    float ia  = g_inv[b * CC + ra];
    float ip  = g_inv[b * CC + rp];
    float in_ = g_inv[b * CC + rn];

    float ssp = 0.0f, ssn = 0.0f;
#pragma unroll
    for (int q = 0; q < 4; q++) {
        int o = lane + 32 * q;
        float4 va = pa[o];
        float4 vp = pp[o];
        float4 vn = pn[o];
        float d;
        d = va.x * ia - vp.x * ip + EPS;  ssp = fmaf(d, d, ssp);
        d = va.y * ia - vp.y * ip + EPS;  ssp = fmaf(d, d, ssp);
        d = va.z * ia - vp.z * ip + EPS;  ssp = fmaf(d, d, ssp);
        d = va.w * ia - vp.w * ip + EPS;  ssp = fmaf(d, d, ssp);
        d = va.x * ia - vn.x * in_ + EPS; ssn = fmaf(d, d, ssn);
        d = va.y * ia - vn.y * in_ + EPS; ssn = fmaf(d, d, ssn);
        d = va.z * ia - vn.z * in_ + EPS; ssn = fmaf(d, d, ssn);
        d = va.w * ia - vn.w * in_ + EPS; ssn = fmaf(d, d, ssn);
    }
#pragma unroll
    for (int off = 16; off; off >>= 1) {
        ssp += __shfl_xor_sync(0xffffffffu, ssp, off);
        ssn += __shfl_xor_sync(0xffffffffu, ssn, off);
    }
    if (lane == 0) {
        float term = sqrtf(ssp) - sqrtf(ssn) + 1.0f;   // margin = 1.0
        term = fmaxf(term, 0.0f);
        atomicAdd(out, term * (1.0f / (float)(BB * TT)));
    }
}

// ---------------------------------------------------------------------------
extern "C" void kernel_launch(void* const* d_in, const int* in_sizes, int n_in,
                              void* d_out, int out_size) {
    const float* emb = (const float*)d_in[0];
    const int*   muc = (const int*)d_in[1];
    const int*   non = (const int*)d_in[2];
    const int*   anc = (const int*)d_in[3];
    const int*   pos = (const int*)d_in[4];
    float* out = (float*)d_out;

    k0_init<<<(BB * MM + 255) / 256, 256>>>(out);
    k1_norm<<<(BB * CC) / 8, 256>>>(emb);
    dim3 g2(NNEG / 128, BB);
    k2_mine<<<g2, 256>>>(emb, muc, non);
    k3_loss<<<(BB * TT * 32 + 255) / 256, 256>>>(emb, muc, non, anc, pos, out);
}

// round 12
// speedup vs baseline: 2.0822x; 2.0491x over previous
#include <cuda_runtime.h>
#include <cuda_bf16.h>
#include <mma.h>
#include <cstdint>

using namespace nvcuda;

#define BB 64
#define CC 2048
#define DD 512
#define MM 128
#define NNEG 1920
#define TT 100
#define EPS 1e-6f

#define NT 128                 // n-tile per block
#define KCH 32                 // K elems per chunk
#define NCHUNK (DD / KCH)      // 16
#define LDT 40                 // operand tile leading dim (bf16): 80B rows
#define LDC 68                 // C leading dim (f32)
#define BSPLIT 8               // batches per k2 launch (8 launches -> ncu catches k2)

// scratch (allocation-free rule: __device__ globals)
__device__ float g_inv[BB * CC];
__device__ unsigned long long g_best[BB * MM];   // (ordered_sim<<32)|(0x7FFFFFFF-n)

__device__ __forceinline__ unsigned ordered_f32(float v) {
    unsigned u = __float_as_uint(v);
    return (u & 0x80000000u) ? ~u : (u | 0x80000000u);
}

// ---------------------------------------------------------------------------
// K0: init scratch + output
// ---------------------------------------------------------------------------
__global__ void k0_init(float* out) {
    int i = blockIdx.x * blockDim.x + threadIdx.x;
    if (i < BB * MM) g_best[i] = 0ULL;
    if (i == 0) out[0] = 0.0f;
}

// ---------------------------------------------------------------------------
// K1: per-row inverse norms (streaming 256MB read)
// ---------------------------------------------------------------------------
__global__ __launch_bounds__(256) void k1_norm(const float* __restrict__ emb) {
    int row  = blockIdx.x * 8 + (threadIdx.x >> 5);
    int lane = threadIdx.x & 31;
    const float4* p = reinterpret_cast<const float4*>(emb + (size_t)row * DD);
    float ss = 0.0f;
#pragma unroll
    for (int q = 0; q < 4; q++) {
        float4 v = p[lane + 32 * q];
        ss += v.x * v.x + v.y * v.y + v.z * v.z + v.w * v.w;
    }
#pragma unroll
    for (int off = 16; off; off >>= 1)
        ss += __shfl_xor_sync(0xffffffffu, ss, off);
    if (lane == 0)
        g_inv[row] = 1.0f / fmaxf(sqrtf(ss), 1e-12f);
}

// ---------------------------------------------------------------------------
// K2: hard-negative mining, bf16 WMMA with register-prefetch pipeline.
// Raw (unnormalized) rows staged as bf16; scale applied in epilogue:
//   argmax_n sim[m][n] == argmax_n raw[m][n]*scB[n]   (ia[m]>0 dropped)
// Block = (batch b0+by, n-tile of 128), 256 threads = 8 warps (2m x 4n),
// warp tile 64x32 = 4x2 wmma 16x16x16 frags.
// ---------------------------------------------------------------------------
__global__ __launch_bounds__(256) void k2_mine(const float* __restrict__ emb,
                                               const int* __restrict__ muc,
                                               const int* __restrict__ non,
                                               int b0) {
    // operand tiles overlaid by C tile (union); C is the larger: 128*68*4 = 34816B
    __shared__ __align__(16) char sbuf[128 * LDC * 4];
    __shared__ int   rA[MM];
    __shared__ int   rB[NT];
    __shared__ float scB[NT];

    __nv_bfloat16* As = reinterpret_cast<__nv_bfloat16*>(sbuf);        // [128][LDT]
    __nv_bfloat16* Bs = As + 128 * LDT;                                // [128][LDT]
    float (*Csh)[LDC] = reinterpret_cast<float (*)[LDC]>(sbuf);        // overlay

    const int b   = b0 + blockIdx.y;
    const int n0  = blockIdx.x * NT;
    const int tid = threadIdx.x;
    const int warp   = tid >> 5;
    const int warp_m = warp >> 2;       // 0..1
    const int warp_n = warp & 3;        // 0..3

    if (tid < 128) {
        rA[tid] = muc[b * MM + tid];
    } else {
        int t2 = tid - 128;
        int r  = non[b * NNEG + n0 + t2];
        rB[t2]  = r;
        scB[t2] = g_inv[b * CC + r];
    }
    __syncthreads();

    // per-thread staging coordinates: 4 float4 per tile per chunk
    // f = tid + 256u : row = f>>3 (0..127), colq = f&7 (float4 col within 32)
    const float* embB = emb + (size_t)b * CC * DD;
    const float4* srcA[4];
    const float4* srcB[4];
    uint32_t dstoff[4];
#pragma unroll
    for (int u = 0; u < 4; u++) {
        int f    = tid + 256 * u;
        int row  = f >> 3;
        int colq = f & 7;
        srcA[u]   = reinterpret_cast<const float4*>(embB + (size_t)rA[row] * DD) + colq;
        srcB[u]   = reinterpret_cast<const float4*>(embB + (size_t)rB[row] * DD) + colq;
        dstoff[u] = row * (LDT * 2) + colq * 8;       // byte offset: 1 float4 -> 4 bf16 = 8B
    }
    char* sAc = reinterpret_cast<char*>(As);
    char* sBc = reinterpret_cast<char*>(Bs);

    wmma::fragment<wmma::accumulator, 16, 16, 16, float> acc[4][2];
#pragma unroll
    for (int i = 0; i < 4; i++)
#pragma unroll
        for (int j = 0; j < 2; j++)
            wmma::fill_fragment(acc[i][j], 0.0f);

    float4 pfa[4], pfb[4];
    // prefetch chunk 0 (k-offset 0, in units of 8 float4 per chunk)
#pragma unroll
    for (int u = 0; u < 4; u++) { pfa[u] = srcA[u][0]; pfb[u] = srcB[u][0]; }

    for (int ch = 0; ch < NCHUNK; ch++) {
        __syncthreads();               // previous mma phase done reading smem
        // commit prefetched regs -> smem (fp32 -> bf16, no scaling)
#pragma unroll
        for (int u = 0; u < 4; u++) {
            __nv_bfloat162 alo = __floats2bfloat162_rn(pfa[u].x, pfa[u].y);
            __nv_bfloat162 ahi = __floats2bfloat162_rn(pfa[u].z, pfa[u].w);
            uint2 wa = { *reinterpret_cast<unsigned*>(&alo), *reinterpret_cast<unsigned*>(&ahi) };
            *reinterpret_cast<uint2*>(sAc + dstoff[u]) = wa;
            __nv_bfloat162 blo = __floats2bfloat162_rn(pfb[u].x, pfb[u].y);
            __nv_bfloat162 bhi = __floats2bfloat162_rn(pfb[u].z, pfb[u].w);
            uint2 wb = { *reinterpret_cast<unsigned*>(&blo), *reinterpret_cast<unsigned*>(&bhi) };
            *reinterpret_cast<uint2*>(sBc + dstoff[u]) = wb;
        }
        __syncthreads();               // tiles ready
        // issue next chunk's loads now; latency overlaps the mma phase below
        if (ch + 1 < NCHUNK) {
            int ko = (ch + 1) * (KCH / 4);          // float4 offset
#pragma unroll
            for (int u = 0; u < 4; u++) { pfa[u] = srcA[u][ko]; pfb[u] = srcB[u][ko]; }
        }
        // mma phase on current smem tiles
#pragma unroll
        for (int kf = 0; kf < KCH / 16; kf++) {
            wmma::fragment<wmma::matrix_a, 16, 16, 16, __nv_bfloat16, wmma::row_major> af[4];
            wmma::fragment<wmma::matrix_b, 16, 16, 16, __nv_bfloat16, wmma::col_major> bf[2];
#pragma unroll
            for (int i = 0; i < 4; i++)
                wmma::load_matrix_sync(af[i], As + (warp_m * 64 + i * 16) * LDT + kf * 16, LDT);
#pragma unroll
            for (int j = 0; j < 2; j++)
                wmma::load_matrix_sync(bf[j], Bs + (warp_n * 32 + j * 16) * LDT + kf * 16, LDT);
#pragma unroll
            for (int i = 0; i < 4; i++)
#pragma unroll
                for (int j = 0; j < 2; j++)
                    wmma::mma_sync(acc[i][j], af[i], bf[j], acc[i][j]);
        }
    }

    // epilogue: two 64-col halves through Csh (overlays operands), per-m argmax
    // compare value = raw_dot * scB[n]  (ia[m] dropped: positive per-m constant)
    const int m_of = tid >> 1;
    const int part = tid & 1;
    float bestv = -1e30f;
    int   besti = 0;

#pragma unroll
    for (int half = 0; half < 2; half++) {
        __syncthreads();
        if ((warp_n >> 1) == half) {
#pragma unroll
            for (int i = 0; i < 4; i++)
#pragma unroll
                for (int j = 0; j < 2; j++)
                    wmma::store_matrix_sync(&Csh[warp_m * 64 + i * 16][(warp_n & 1) * 32 + j * 16],
                                            acc[i][j], LDC, wmma::mem_row_major);
        }
        __syncthreads();
#pragma unroll 8
        for (int jj = 0; jj < 32; jj++) {
            int  col = part * 32 + jj;
            float v  = Csh[m_of][col] * scB[half * 64 + col];
            int  gn  = n0 + half * 64 + col;
            if (v > bestv) { bestv = v; besti = gn; }   // ascending -> first max on ties
        }
    }
    // merge lane pairs (2t, 2t+1 share m)
    float ov = __shfl_xor_sync(0xffffffffu, bestv, 1);
    int   oi = __shfl_xor_sync(0xffffffffu, besti, 1);
    if (ov > bestv || (ov == bestv && oi < besti)) { bestv = ov; besti = oi; }
    if (part == 0) {
        unsigned long long key =
            ((unsigned long long)ordered_f32(bestv) << 32) |
            (unsigned)(0x7FFFFFFFu - besti);
        atomicMax(&g_best[b * MM + m_of], key);
    }
}

// ---------------------------------------------------------------------------
// K3: loss. One warp per (b,t): d_pos, d_neg (exact fp32), relu, atomicAdd.
// ---------------------------------------------------------------------------
__global__ __launch_bounds__(256) void k3_loss(const float* __restrict__ emb,
                                               const int* __restrict__ muc,
                                               const int* __restrict__ non,
                                               const int* __restrict__ anc,
                                               const int* __restrict__ pos,
                                               float* __restrict__ out) {
    int g    = blockIdx.x * blockDim.x + threadIdx.x;
    int w    = g >> 5;
    int lane = g & 31;
    if (w >= BB * TT) return;
    int b = w / TT;
    int t = w % TT;

    int m  = anc[b * TT + t];
    int ra = muc[b * MM + m];
    int rp = muc[b * MM + pos[b * TT + t]];

    unsigned long long key = g_best[b * MM + m];
    int n  = (int)(0x7FFFFFFFu - (unsigned)(key & 0xFFFFFFFFu));
    int rn = non[b * NNEG + n];

    const float4* pa = reinterpret_cast<const float4*>(emb + ((size_t)b * CC + ra) * DD);
    const float4* pp = reinterpret_cast<const float4*>(emb + ((size_t)b * CC + rp) * DD);
    const float4* pn = reinterpret_cast<const float4*>(emb + ((size_t)b * CC + rn) * DD);
    float ia  = g_inv[b * CC + ra];
    float ip  = g_inv[b * CC + rp];
    float in_ = g_inv[b * CC + rn];

    float ssp = 0.0f, ssn = 0.0f;
#pragma unroll
    for (int q = 0; q < 4; q++) {
        int o = lane + 32 * q;
        float4 va = pa[o];
        float4 vp = pp[o];
        float4 vn = pn[o];
        float d;
        d = va.x * ia - vp.x * ip + EPS;  ssp = fmaf(d, d, ssp);
        d = va.y * ia - vp.y * ip + EPS;  ssp = fmaf(d, d, ssp);
        d = va.z * ia - vp.z * ip + EPS;  ssp = fmaf(d, d, ssp);
        d = va.w * ia - vp.w * ip + EPS;  ssp = fmaf(d, d, ssp);
        d = va.x * ia - vn.x * in_ + EPS; ssn = fmaf(d, d, ssn);
        d = va.y * ia - vn.y * in_ + EPS; ssn = fmaf(d, d, ssn);
        d = va.z * ia - vn.z * in_ + EPS; ssn = fmaf(d, d, ssn);
        d = va.w * ia - vn.w * in_ + EPS; ssn = fmaf(d, d, ssn);
    }
#pragma unroll
    for (int off = 16; off; off >>= 1) {
        ssp += __shfl_xor_sync(0xffffffffu, ssp, off);
        ssn += __shfl_xor_sync(0xffffffffu, ssn, off);
    }
    if (lane == 0) {
        float term = sqrtf(ssp) - sqrtf(ssn) + 1.0f;   // margin = 1.0
        term = fmaxf(term, 0.0f);
        atomicAdd(out, term * (1.0f / (float)(BB * TT)));
    }
}

// ---------------------------------------------------------------------------
extern "C" void kernel_launch(void* const* d_in, const int* in_sizes, int n_in,
                              void* d_out, int out_size) {
    const float* emb = (const float*)d_in[0];
    const int*   muc = (const int*)d_in[1];
    const int*   non = (const int*)d_in[2];
    const int*   anc = (const int*)d_in[3];
    const int*   pos = (const int*)d_in[4];
    float* out = (float*)d_out;

    k0_init<<<(BB * MM + 255) / 256, 256>>>(out);
    k1_norm<<<(BB * CC) / 8, 256>>>(emb);
    dim3 g2(NNEG / NT, BSPLIT);
    for (int b0 = 0; b0 < BB; b0 += BSPLIT)
        k2_mine<<<g2, 256>>>(emb, muc, non, b0);
    k3_loss<<<(BB * TT * 32 + 255) / 256, 256>>>(emb, muc, non, anc, pos, out);
}

// round 14
// speedup vs baseline: 3.1582x; 1.5167x over previous
#include <cuda_runtime.h>
#include <cuda_bf16.h>
#include <mma.h>
#include <cstdint>

using namespace nvcuda;

#define BB 64
#define CC 2048
#define DD 512
#define MM 128
#define NNEG 1920
#define TT 100
#define EPS 1e-6f

#define NT 128                 // n-tile per block
#define KCH 32                 // K elems per chunk
#define NCHUNK (DD / KCH)      // 16
#define LDT 40                 // operand tile leading dim (bf16): 80B rows
#define LDC 68                 // C leading dim (f32)

// scratch (allocation-free rule: __device__ globals)
__device__ float g_inv[BB * CC];
__device__ unsigned long long g_best[BB * MM];   // (ordered_sim<<32)|(0x7FFFFFFF-n)

__device__ __forceinline__ unsigned ordered_f32(float v) {
    unsigned u = __float_as_uint(v);
    return (u & 0x80000000u) ? ~u : (u | 0x80000000u);
}

// ---------------------------------------------------------------------------
// K0: init scratch + output
// ---------------------------------------------------------------------------
__global__ void k0_init(float* out) {
    int i = blockIdx.x * blockDim.x + threadIdx.x;
    if (i < BB * MM) g_best[i] = 0ULL;
    if (i == 0) out[0] = 0.0f;
}

// ---------------------------------------------------------------------------
// K1: per-row inverse norms (streaming 256MB read)
// ---------------------------------------------------------------------------
__global__ __launch_bounds__(256) void k1_norm(const float* __restrict__ emb) {
    int row  = blockIdx.x * 8 + (threadIdx.x >> 5);
    int lane = threadIdx.x & 31;
    const float4* p = reinterpret_cast<const float4*>(emb + (size_t)row * DD);
    float ss = 0.0f;
#pragma unroll
    for (int q = 0; q < 4; q++) {
        float4 v = p[lane + 32 * q];
        ss += v.x * v.x + v.y * v.y + v.z * v.z + v.w * v.w;
    }
#pragma unroll
    for (int off = 16; off; off >>= 1)
        ss += __shfl_xor_sync(0xffffffffu, ss, off);
    if (lane == 0)
        g_inv[row] = 1.0f / fmaxf(sqrtf(ss), 1e-12f);
}

// ---------------------------------------------------------------------------
// K2: hard-negative mining, bf16 WMMA with register-prefetch pipeline.
// Raw (unnormalized) rows staged as bf16; scale applied in epilogue:
//   argmax_n sim[m][n] == argmax_n raw[m][n]*scB[n]   (ia[m]>0 dropped)
// Block = (batch blockIdx.y, n-tile of 128), 256 threads = 8 warps (2m x 4n),
// warp tile 64x32 = 4x2 wmma 16x16x16 frags.
// __launch_bounds__(256,2): cap regs at 128 -> 2 blocks/SM so one block's
// staging overlaps the other's mma phase (R12 profile: occ 12.5%, all pipes
// <16% busy = single-block latency-bound).
// ---------------------------------------------------------------------------
__global__ __launch_bounds__(256, 2) void k2_mine(const float* __restrict__ emb,
                                                  const int* __restrict__ muc,
                                                  const int* __restrict__ non) {
    // operand tiles overlaid by C tile (union); C is the larger: 128*68*4 = 34816B
    __shared__ __align__(16) char sbuf[128 * LDC * 4];
    __shared__ int   rA[MM];
    __shared__ int   rB[NT];
    __shared__ float scB[NT];

    __nv_bfloat16* As = reinterpret_cast<__nv_bfloat16*>(sbuf);        // [128][LDT]
    __nv_bfloat16* Bs = As + 128 * LDT;                                // [128][LDT]
    float (*Csh)[LDC] = reinterpret_cast<float (*)[LDC]>(sbuf);        // overlay

    const int b   = blockIdx.y;
    const int n0  = blockIdx.x * NT;
    const int tid = threadIdx.x;
    const int warp   = tid >> 5;
    const int warp_m = warp >> 2;       // 0..1
    const int warp_n = warp & 3;        // 0..3

    if (tid < 128) {
        rA[tid] = muc[b * MM + tid];
    } else {
        int t2 = tid - 128;
        int r  = non[b * NNEG + n0 + t2];
        rB[t2]  = r;
        scB[t2] = g_inv[b * CC + r];
    }
    __syncthreads();

    // per-thread staging coordinates: 4 float4 per tile per chunk
    // f = tid + 256u : row = f>>3 (0..127), colq = f&7 (float4 col within 32)
    const float* embB = emb + (size_t)b * CC * DD;
    const float4* srcA[4];
    const float4* srcB[4];
    uint32_t dstoff[4];
#pragma unroll
    for (int u = 0; u < 4; u++) {
        int f    = tid + 256 * u;
        int row  = f >> 3;
        int colq = f & 7;
        srcA[u]   = reinterpret_cast<const float4*>(embB + (size_t)rA[row] * DD) + colq;
        srcB[u]   = reinterpret_cast<const float4*>(embB + (size_t)rB[row] * DD) + colq;
        dstoff[u] = row * (LDT * 2) + colq * 8;       // byte offset: 1 float4 -> 4 bf16 = 8B
    }
    char* sAc = reinterpret_cast<char*>(As);
    char* sBc = reinterpret_cast<char*>(Bs);

    wmma::fragment<wmma::accumulator, 16, 16, 16, float> acc[4][2];
#pragma unroll
    for (int i = 0; i < 4; i++)
#pragma unroll
        for (int j = 0; j < 2; j++)
            wmma::fill_fragment(acc[i][j], 0.0f);

    float4 pfa[4], pfb[4];
    // prefetch chunk 0 (k-offset 0, in units of 8 float4 per chunk)
#pragma unroll
    for (int u = 0; u < 4; u++) { pfa[u] = srcA[u][0]; pfb[u] = srcB[u][0]; }

    for (int ch = 0; ch < NCHUNK; ch++) {
        __syncthreads();               // previous mma phase done reading smem
        // commit prefetched regs -> smem (fp32 -> bf16, no scaling)
#pragma unroll
        for (int u = 0; u < 4; u++) {
            __nv_bfloat162 alo = __floats2bfloat162_rn(pfa[u].x, pfa[u].y);
            __nv_bfloat162 ahi = __floats2bfloat162_rn(pfa[u].z, pfa[u].w);
            uint2 wa = { *reinterpret_cast<unsigned*>(&alo), *reinterpret_cast<unsigned*>(&ahi) };
            *reinterpret_cast<uint2*>(sAc + dstoff[u]) = wa;
            __nv_bfloat162 blo = __floats2bfloat162_rn(pfb[u].x, pfb[u].y);
            __nv_bfloat162 bhi = __floats2bfloat162_rn(pfb[u].z, pfb[u].w);
            uint2 wb = { *reinterpret_cast<unsigned*>(&blo), *reinterpret_cast<unsigned*>(&bhi) };
            *reinterpret_cast<uint2*>(sBc + dstoff[u]) = wb;
        }
        __syncthreads();               // tiles ready
        // issue next chunk's loads now; latency overlaps the mma phase below
        if (ch + 1 < NCHUNK) {
            int ko = (ch + 1) * (KCH / 4);          // float4 offset
#pragma unroll
            for (int u = 0; u < 4; u++) { pfa[u] = srcA[u][ko]; pfb[u] = srcB[u][ko]; }
        }
        // mma phase on current smem tiles
#pragma unroll
        for (int kf = 0; kf < KCH / 16; kf++) {
            wmma::fragment<wmma::matrix_a, 16, 16, 16, __nv_bfloat16, wmma::row_major> af[4];
            wmma::fragment<wmma::matrix_b, 16, 16, 16, __nv_bfloat16, wmma::col_major> bf[2];
#pragma unroll
            for (int i = 0; i < 4; i++)
                wmma::load_matrix_sync(af[i], As + (warp_m * 64 + i * 16) * LDT + kf * 16, LDT);
#pragma unroll
            for (int j = 0; j < 2; j++)
                wmma::load_matrix_sync(bf[j], Bs + (warp_n * 32 + j * 16) * LDT + kf * 16, LDT);
#pragma unroll
            for (int i = 0; i < 4; i++)
#pragma unroll
                for (int j = 0; j < 2; j++)
                    wmma::mma_sync(acc[i][j], af[i], bf[j], acc[i][j]);
        }
    }

    // epilogue: two 64-col halves through Csh (overlays operands), per-m argmax
    // compare value = raw_dot * scB[n]  (ia[m] dropped: positive per-m constant)
    const int m_of = tid >> 1;
    const int part = tid & 1;
    float bestv = -1e30f;
    int   besti = 0;

#pragma unroll
    for (int half = 0; half < 2; half++) {
        __syncthreads();
        if ((warp_n >> 1) == half) {
#pragma unroll
            for (int i = 0; i < 4; i++)
#pragma unroll
                for (int j = 0; j < 2; j++)
                    wmma::store_matrix_sync(&Csh[warp_m * 64 + i * 16][(warp_n & 1) * 32 + j * 16],
                                            acc[i][j], LDC, wmma::mem_row_major);
        }
        __syncthreads();
#pragma unroll 8
        for (int jj = 0; jj < 32; jj++) {
            int  col = part * 32 + jj;
            float v  = Csh[m_of][col] * scB[half * 64 + col];
            int  gn  = n0 + half * 64 + col;
            if (v > bestv) { bestv = v; besti = gn; }   // ascending -> first max on ties
        }
    }
    // merge lane pairs (2t, 2t+1 share m)
    float ov = __shfl_xor_sync(0xffffffffu, bestv, 1);
    int   oi = __shfl_xor_sync(0xffffffffu, besti, 1);
    if (ov > bestv || (ov == bestv && oi < besti)) { bestv = ov; besti = oi; }
    if (part == 0) {
        unsigned long long key =
            ((unsigned long long)ordered_f32(bestv) << 32) |
            (unsigned)(0x7FFFFFFFu - besti);
        atomicMax(&g_best[b * MM + m_of], key);
    }
}

// ---------------------------------------------------------------------------
// K3: loss. One warp per (b,t): d_pos, d_neg (exact fp32), relu, atomicAdd.
// ---------------------------------------------------------------------------
__global__ __launch_bounds__(256) void k3_loss(const float* __restrict__ emb,
                                               const int* __restrict__ muc,
                                               const int* __restrict__ non,
                                               const int* __restrict__ anc,
                                               const int* __restrict__ pos,
                                               float* __restrict__ out) {
    int g    = blockIdx.x * blockDim.x + threadIdx.x;
    int w    = g >> 5;
    int lane = g & 31;
    if (w >= BB * TT) return;
    int b = w / TT;
    int t = w % TT;

    int m  = anc[b * TT + t];
    int ra = muc[b * MM + m];
    int rp = muc[b * MM + pos[b * TT + t]];

    unsigned long long key = g_best[b * MM + m];
    int n  = (int)(0x7FFFFFFFu - (unsigned)(key & 0xFFFFFFFFu));
    int rn = non[b * NNEG + n];

    const float4* pa = reinterpret_cast<const float4*>(emb + ((size_t)b * CC + ra) * DD);
    const float4* pp = reinterpret_cast<const float4*>(emb + ((size_t)b * CC + rp) * DD);
    const float4* pn = reinterpret_cast<const float4*>(emb + ((size_t)b * CC + rn) * DD);
    float ia  = g_inv[b * CC + ra];
    float ip  = g_inv[b * CC + rp];
    float in_ = g_inv[b * CC + rn];

    float ssp = 0.0f, ssn = 0.0f;
#pragma unroll
    for (int q = 0; q < 4; q++) {
        int o = lane + 32 * q;
        float4 va = pa[o];
        float4 vp = pp[o];
        float4 vn = pn[o];
        float d;
        d = va.x * ia - vp.x * ip + EPS;  ssp = fmaf(d, d, ssp);
        d = va.y * ia - vp.y * ip + EPS;  ssp = fmaf(d, d, ssp);
        d = va.z * ia - vp.z * ip + EPS;  ssp = fmaf(d, d, ssp);
        d = va.w * ia - vp.w * ip + EPS;  ssp = fmaf(d, d, ssp);
        d = va.x * ia - vn.x * in_ + EPS; ssn = fmaf(d, d, ssn);
        d = va.y * ia - vn.y * in_ + EPS; ssn = fmaf(d, d, ssn);
        d = va.z * ia - vn.z * in_ + EPS; ssn = fmaf(d, d, ssn);
        d = va.w * ia - vn.w * in_ + EPS; ssn = fmaf(d, d, ssn);
    }
#pragma unroll
    for (int off = 16; off; off >>= 1) {
        ssp += __shfl_xor_sync(0xffffffffu, ssp, off);
        ssn += __shfl_xor_sync(0xffffffffu, ssn, off);
    }
    if (lane == 0) {
        float term = sqrtf(ssp) - sqrtf(ssn) + 1.0f;   // margin = 1.0
        term = fmaxf(term, 0.0f);
        atomicAdd(out, term * (1.0f / (float)(BB * TT)));
    }
}

// ---------------------------------------------------------------------------
extern "C" void kernel_launch(void* const* d_in, const int* in_sizes, int n_in,
                              void* d_out, int out_size) {
    const float* emb = (const float*)d_in[0];
    const int*   muc = (const int*)d_in[1];
    const int*   non = (const int*)d_in[2];
    const int*   anc = (const int*)d_in[3];
    const int*   pos = (const int*)d_in[4];
    float* out = (float*)d_out;

    k0_init<<<(BB * MM + 255) / 256, 256>>>(out);
    k1_norm<<<(BB * CC) / 8, 256>>>(emb);
    dim3 g2(NNEG / NT, BB);
    k2_mine<<<g2, 256>>>(emb, muc, non);
    k3_loss<<<(BB * TT * 32 + 255) / 256, 256>>>(emb, muc, non, anc, pos, out);
}